// round 8
// baseline (speedup 1.0000x reference)
#include <cuda_runtime.h>

#define HWD   256
#define HW2   65536            // HWD*HWD
#define NB    8
#define NC    64
#define NPIX  (NB*HW2)         // 524288
#define HW24  16384            // quads per batch
#define NORM_BLKS 256          // blocks 0..255: norm   (256 blk * 64 quads = 16384)
#define BLEND_BLKS 256         // blocks 256..511: blend (65536 thr = 16384 quads * 4 grp)

// Scratch (static device globals — allocation-free)
__device__ float g_n1[NPIX];
__device__ float g_n2[NPIX];

// ---------------------------------------------------------------------------
// Fused-phase pipelined kernel.
//   blocks [0,256):    channel L1 norm of batch nb   (if nb >= 0)
//   blocks [256,512):  conv+ratio+blend of batch bb  (if bb >= 0)
// blend(bb) depends only on g_n written by the PREVIOUS launch -> single
// stream, no events. Norm reads default-cached (keep chunk in L2 for next
// launch's blend); blend reads __ldcs (dead), out stores __stcs (streaming).
// ---------------------------------------------------------------------------
__global__ __launch_bounds__(256) void k_pipe(const float4* __restrict__ x1,
                                              const float4* __restrict__ x2,
                                              float4* __restrict__ out,
                                              const float* __restrict__ w,
                                              const float* __restrict__ bias,
                                              int nb, int bb) {
    int t = threadIdx.x;

    if (blockIdx.x < NORM_BLKS) {
        // ---------------- norm phase: batch nb ----------------
        if (nb < 0) return;
        __shared__ float4 sm1[4][64];
        __shared__ float4 sm2[4][64];
        int p = t & 63;                  // quad within block
        int g = t >> 6;                  // 16-channel group 0..3
        int q = blockIdx.x * 64 + p;     // [0, HW24)
        size_t base = ((size_t)nb * NC + g * 16) * HW24 + q;
        const float4* p1 = x1 + base;
        const float4* p2 = x2 + base;

        float4 s1 = make_float4(0.f, 0.f, 0.f, 0.f);
        float4 s2 = make_float4(0.f, 0.f, 0.f, 0.f);
#pragma unroll
        for (int c = 0; c < 16; ++c) {
            float4 a = p1[(size_t)c * HW24];
            float4 d = p2[(size_t)c * HW24];
            s1.x += fabsf(a.x); s1.y += fabsf(a.y); s1.z += fabsf(a.z); s1.w += fabsf(a.w);
            s2.x += fabsf(d.x); s2.y += fabsf(d.y); s2.z += fabsf(d.z); s2.w += fabsf(d.w);
        }
        sm1[g][p] = s1;
        sm2[g][p] = s2;
        __syncthreads();

        if (t < 64) {
            float4 a = sm1[0][t], b2 = sm1[1][t], c2 = sm1[2][t], d2 = sm1[3][t];
            float4 o;
            o.x = (a.x + b2.x) + (c2.x + d2.x);
            o.y = (a.y + b2.y) + (c2.y + d2.y);
            o.z = (a.z + b2.z) + (c2.z + d2.z);
            o.w = (a.w + b2.w) + (c2.w + d2.w);
            reinterpret_cast<float4*>(g_n1)[nb * HW24 + blockIdx.x * 64 + t] = o;
        } else if (t < 128) {
            int tt = t - 64;
            float4 a = sm2[0][tt], b2 = sm2[1][tt], c2 = sm2[2][tt], d2 = sm2[3][tt];
            float4 o;
            o.x = (a.x + b2.x) + (c2.x + d2.x);
            o.y = (a.y + b2.y) + (c2.y + d2.y);
            o.z = (a.z + b2.z) + (c2.z + d2.z);
            o.w = (a.w + b2.w) + (c2.w + d2.w);
            reinterpret_cast<float4*>(g_n2)[nb * HW24 + blockIdx.x * 64 + tt] = o;
        }
        return;
    }

    // ---------------- blend phase: batch bb (conv+ratio inline) ----------------
    if (bb < 0) return;
    int i = (blockIdx.x - NORM_BLKS) * 256 + t;  // [0, 65536)
    int q = i & (HW24 - 1);      // quad within batch
    int g = i >> 14;             // 16-channel group 0..3
    int y  = q >> 6;             // pixel row
    int x0 = (q & 63) * 4;       // first pixel column of the quad

    // 3x3 conv over g_n1/g_n2 (zero pad), accumulated row-wise for 4 lanes.
    float w0 = __ldg(w+0), w1 = __ldg(w+1), w2 = __ldg(w+2);
    float w3 = __ldg(w+3), w4 = __ldg(w+4), w5 = __ldg(w+5);
    float w6 = __ldg(w+6), w7 = __ldg(w+7), w8 = __ldg(w+8);
    float bv = __ldg(bias);

    const float* n1 = g_n1 + bb * HW2;
    const float* n2 = g_n2 + bb * HW2;

    float c1a0 = 0.f, c1a1 = 0.f, c1a2 = 0.f, c1a3 = 0.f;
    float c2a0 = 0.f, c2a1 = 0.f, c2a2 = 0.f, c2a3 = 0.f;
    bool xm = (x0 > 0), xp = (x0 < HWD - 4);
#pragma unroll
    for (int dy = 0; dy < 3; ++dy) {
        int row = y + dy - 1;
        bool vr = (row >= 0) && (row < HWD);
        int rb = row * HWD + x0;
        float a0 = (vr && xm) ? n1[rb - 1] : 0.f;
        float a1 = vr ? n1[rb + 0] : 0.f;
        float a2 = vr ? n1[rb + 1] : 0.f;
        float a3 = vr ? n1[rb + 2] : 0.f;
        float a4 = vr ? n1[rb + 3] : 0.f;
        float a5 = (vr && xp) ? n1[rb + 4] : 0.f;
        float e0 = (vr && xm) ? n2[rb - 1] : 0.f;
        float e1 = vr ? n2[rb + 0] : 0.f;
        float e2 = vr ? n2[rb + 1] : 0.f;
        float e3 = vr ? n2[rb + 2] : 0.f;
        float e4 = vr ? n2[rb + 3] : 0.f;
        float e5 = (vr && xp) ? n2[rb + 4] : 0.f;
        float wa = (dy == 0) ? w0 : (dy == 1) ? w3 : w6;
        float wb = (dy == 0) ? w1 : (dy == 1) ? w4 : w7;
        float wc = (dy == 0) ? w2 : (dy == 1) ? w5 : w8;
        c1a0 += wa * a0 + wb * a1 + wc * a2;
        c1a1 += wa * a1 + wb * a2 + wc * a3;
        c1a2 += wa * a2 + wb * a3 + wc * a4;
        c1a3 += wa * a3 + wb * a4 + wc * a5;
        c2a0 += wa * e0 + wb * e1 + wc * e2;
        c2a1 += wa * e1 + wb * e2 + wc * e3;
        c2a2 += wa * e2 + wb * e3 + wc * e4;
        c2a3 += wa * e3 + wb * e4 + wc * e5;
    }
    float4 r1, r2;
    {
        float t1, t2;
        t1 = c1a0 + bv; t2 = c2a0 + bv; r1.x = t1 / (t1 + t2); r2.x = 1.f - r1.x;
        t1 = c1a1 + bv; t2 = c2a1 + bv; r1.y = t1 / (t1 + t2); r2.y = 1.f - r1.y;
        t1 = c1a2 + bv; t2 = c2a2 + bv; r1.z = t1 / (t1 + t2); r2.z = 1.f - r1.z;
        t1 = c1a3 + bv; t2 = c2a3 + bv; r1.w = t1 / (t1 + t2); r2.w = 1.f - r1.w;
    }

    size_t base = ((size_t)bb * NC + g * 16) * HW24 + q;
#pragma unroll 8
    for (int c = 0; c < 16; ++c) {
        float4 a = __ldcs(x1 + base + (size_t)c * HW24);
        float4 d = __ldcs(x2 + base + (size_t)c * HW24);
        float4 o;
        o.x = a.x * r1.x + d.x * r2.x;
        o.y = a.y * r1.y + d.y * r2.y;
        o.z = a.z * r1.z + d.z * r2.z;
        o.w = a.w * r1.w + d.w * r2.w;
        __stcs(out + base + (size_t)c * HW24, o);
    }
}

extern "C" void kernel_launch(void* const* d_in, const int* in_sizes, int n_in,
                              void* d_out, int out_size) {
    const float4* x1 = (const float4*)d_in[0];
    const float4* x2 = (const float4*)d_in[1];
    const float*  w  = (const float*)d_in[2];
    const float*  bv = (const float*)d_in[3];
    float4* out = (float4*)d_out;

    // Software-pipelined over batches: launch c does norm(c) + blend(c-1).
    for (int c = 0; c <= NB; ++c) {
        int nb = (c < NB) ? c : -1;
        int bb = (c > 0) ? (c - 1) : -1;
        k_pipe<<<NORM_BLKS + BLEND_BLKS, 256>>>(x1, x2, out, w, bv, nb, bb);
    }
}

// round 9
// speedup vs baseline: 1.0509x; 1.0509x over previous
#include <cuda_runtime.h>

#define HWD   256
#define HW2   65536            // HWD*HWD
#define NB    8
#define NC    64
#define NPIX  (NB*HW2)         // 524288
#define HW24  16384            // float4-quads per batch image
#define GRID  512              // must be <= 148*4 so all CTAs are co-resident
#define NTHR  256

// Scratch + barrier state (static device globals — allocation-free)
__device__ float g_n1[NPIX];
__device__ float g_n2[NPIX];
__device__ volatile unsigned g_gen;   // barrier generation (sense)
__device__ unsigned g_cnt;            // barrier arrival counter

// ---------------------------------------------------------------------------
// Software grid barrier (sense-reversal). Safe because GRID=512 CTAs at
// <=4 CTAs/SM (__launch_bounds__(256,4)) are all co-resident on 148 SMs.
// Release: all block stores ordered by __syncthreads, published by tid0's
// __threadfence before the atomic arrive. Acquire: fence after the spin.
// ---------------------------------------------------------------------------
__device__ __forceinline__ void grid_barrier() {
    __syncthreads();
    if (threadIdx.x == 0) {
        __threadfence();
        unsigned my = g_gen;
        if (atomicAdd(&g_cnt, 1) == GRID - 1) {
            g_cnt = 0;
            __threadfence();
            g_gen = my + 1;
        } else {
            while (g_gen == my) __nanosleep(64);
        }
        __threadfence();
    }
    __syncthreads();
}

// ---------------------------------------------------------------------------
// Norm phase for batch b: per-pixel channel L1 norms of x1 and x2.
// Block = 32 quads x 8 groups of 8 channels, smem combine.
// Default-cached reads: batch b's x lines stay in L2 for the blend phase.
// ---------------------------------------------------------------------------
__device__ __forceinline__ void do_norm(const float4* __restrict__ x1,
                                        const float4* __restrict__ x2,
                                        int b,
                                        float4 (*sm1)[32], float4 (*sm2)[32]) {
    int t = threadIdx.x;
    int p = t & 31;                  // quad within block
    int g = t >> 5;                  // channel group 0..7
    int q = blockIdx.x * 32 + p;     // [0, HW24)
    size_t base = ((size_t)b * NC + g * 8) * HW24 + q;

    float4 s1 = make_float4(0.f, 0.f, 0.f, 0.f);
    float4 s2 = make_float4(0.f, 0.f, 0.f, 0.f);
#pragma unroll
    for (int c = 0; c < 8; ++c) {
        float4 a = x1[base + (size_t)c * HW24];
        float4 d = x2[base + (size_t)c * HW24];
        s1.x += fabsf(a.x); s1.y += fabsf(a.y); s1.z += fabsf(a.z); s1.w += fabsf(a.w);
        s2.x += fabsf(d.x); s2.y += fabsf(d.y); s2.z += fabsf(d.z); s2.w += fabsf(d.w);
    }
    sm1[g][p] = s1;
    sm2[g][p] = s2;
    __syncthreads();

    if (t < 32) {
        float4 o = make_float4(0.f, 0.f, 0.f, 0.f);
#pragma unroll
        for (int k = 0; k < 8; ++k) {
            float4 v = sm1[k][t];
            o.x += v.x; o.y += v.y; o.z += v.z; o.w += v.w;
        }
        reinterpret_cast<float4*>(g_n1)[b * HW24 + blockIdx.x * 32 + t] = o;
    } else if (t < 64) {
        int tt = t - 32;
        float4 o = make_float4(0.f, 0.f, 0.f, 0.f);
#pragma unroll
        for (int k = 0; k < 8; ++k) {
            float4 v = sm2[k][tt];
            o.x += v.x; o.y += v.y; o.z += v.z; o.w += v.w;
        }
        reinterpret_cast<float4*>(g_n2)[b * HW24 + blockIdx.x * 32 + tt] = o;
    }
    // smem reuse across iterations is protected by the grid_barrier's
    // __syncthreads before the next do_norm.
}

// ---------------------------------------------------------------------------
// Blend phase for batch b: 3x3 conv + bias on g_n1/g_n2 computed inline,
// then out = x1*r1 + x2*(1-r1). Thread = one quad x one 8-channel group.
// x re-reads hit L2 (just streamed by norm(b)); __ldcs marks them dead,
// __stcs keeps out stores from polluting L2.
// ---------------------------------------------------------------------------
__device__ __forceinline__ void do_blend(const float4* __restrict__ x1,
                                         const float4* __restrict__ x2,
                                         float4* __restrict__ out,
                                         const float* __restrict__ w,
                                         const float* __restrict__ bias,
                                         int b) {
    int i = blockIdx.x * NTHR + threadIdx.x;   // [0, 131072)
    int q = i & (HW24 - 1);      // quad within batch image
    int g = i >> 14;             // channel group 0..7
    int y  = q >> 6;             // pixel row
    int x0 = (q & 63) * 4;       // first pixel column of the quad

    float w0 = __ldg(w+0), w1 = __ldg(w+1), w2 = __ldg(w+2);
    float w3 = __ldg(w+3), w4 = __ldg(w+4), w5 = __ldg(w+5);
    float w6 = __ldg(w+6), w7 = __ldg(w+7), w8 = __ldg(w+8);
    float bv = __ldg(bias);

    const float* n1 = g_n1 + b * HW2;
    const float* n2 = g_n2 + b * HW2;

    float c1a0 = 0.f, c1a1 = 0.f, c1a2 = 0.f, c1a3 = 0.f;
    float c2a0 = 0.f, c2a1 = 0.f, c2a2 = 0.f, c2a3 = 0.f;
    bool xm = (x0 > 0), xp = (x0 < HWD - 4);
#pragma unroll
    for (int dy = 0; dy < 3; ++dy) {
        int row = y + dy - 1;
        bool vr = (row >= 0) && (row < HWD);
        int rb = row * HWD + x0;
        float a0 = (vr && xm) ? n1[rb - 1] : 0.f;
        float a1 = vr ? n1[rb + 0] : 0.f;
        float a2 = vr ? n1[rb + 1] : 0.f;
        float a3 = vr ? n1[rb + 2] : 0.f;
        float a4 = vr ? n1[rb + 3] : 0.f;
        float a5 = (vr && xp) ? n1[rb + 4] : 0.f;
        float e0 = (vr && xm) ? n2[rb - 1] : 0.f;
        float e1 = vr ? n2[rb + 0] : 0.f;
        float e2 = vr ? n2[rb + 1] : 0.f;
        float e3 = vr ? n2[rb + 2] : 0.f;
        float e4 = vr ? n2[rb + 3] : 0.f;
        float e5 = (vr && xp) ? n2[rb + 4] : 0.f;
        float wa = (dy == 0) ? w0 : (dy == 1) ? w3 : w6;
        float wb = (dy == 0) ? w1 : (dy == 1) ? w4 : w7;
        float wc = (dy == 0) ? w2 : (dy == 1) ? w5 : w8;
        c1a0 += wa * a0 + wb * a1 + wc * a2;
        c1a1 += wa * a1 + wb * a2 + wc * a3;
        c1a2 += wa * a2 + wb * a3 + wc * a4;
        c1a3 += wa * a3 + wb * a4 + wc * a5;
        c2a0 += wa * e0 + wb * e1 + wc * e2;
        c2a1 += wa * e1 + wb * e2 + wc * e3;
        c2a2 += wa * e2 + wb * e3 + wc * e4;
        c2a3 += wa * e3 + wb * e4 + wc * e5;
    }
    float4 r1, r2;
    {
        float t1, t2;
        t1 = c1a0 + bv; t2 = c2a0 + bv; r1.x = t1 / (t1 + t2); r2.x = 1.f - r1.x;
        t1 = c1a1 + bv; t2 = c2a1 + bv; r1.y = t1 / (t1 + t2); r2.y = 1.f - r1.y;
        t1 = c1a2 + bv; t2 = c2a2 + bv; r1.z = t1 / (t1 + t2); r2.z = 1.f - r1.z;
        t1 = c1a3 + bv; t2 = c2a3 + bv; r1.w = t1 / (t1 + t2); r2.w = 1.f - r1.w;
    }

    size_t base = ((size_t)b * NC + g * 8) * HW24 + q;
#pragma unroll
    for (int c = 0; c < 8; ++c) {
        float4 a = __ldcs(x1 + base + (size_t)c * HW24);
        float4 d = __ldcs(x2 + base + (size_t)c * HW24);
        float4 o;
        o.x = a.x * r1.x + d.x * r2.x;
        o.y = a.y * r1.y + d.y * r2.y;
        o.z = a.z * r1.z + d.z * r2.z;
        o.w = a.w * r1.w + d.w * r2.w;
        __stcs(out + base + (size_t)c * HW24, o);
    }
}

// ---------------------------------------------------------------------------
// Persistent pipelined kernel: one launch, 8 batches.
//   norm(0); for b: barrier; blend(b); norm(b+1);
// blend(b) reads the x lines norm(b) just left in L2 -> x hits DRAM once.
// ---------------------------------------------------------------------------
__global__ __launch_bounds__(NTHR, 4) void k_fused(const float4* __restrict__ x1,
                                                   const float4* __restrict__ x2,
                                                   float4* __restrict__ out,
                                                   const float* __restrict__ w,
                                                   const float* __restrict__ bias) {
    __shared__ float4 sm1[8][32];
    __shared__ float4 sm2[8][32];

    do_norm(x1, x2, 0, sm1, sm2);
    for (int b = 0; b < NB; ++b) {
        grid_barrier();
        do_blend(x1, x2, out, w, bias, b);
        if (b + 1 < NB)
            do_norm(x1, x2, b + 1, sm1, sm2);
    }
}

extern "C" void kernel_launch(void* const* d_in, const int* in_sizes, int n_in,
                              void* d_out, int out_size) {
    const float4* x1 = (const float4*)d_in[0];
    const float4* x2 = (const float4*)d_in[1];
    const float*  w  = (const float*)d_in[2];
    const float*  bv = (const float*)d_in[3];
    float4* out = (float4*)d_out;

    k_fused<<<GRID, NTHR>>>(x1, x2, out, w, bv);
}

// round 10
// speedup vs baseline: 1.0866x; 1.0339x over previous
#include <cuda_runtime.h>

#define HWD   256
#define HW2   65536            // HWD*HWD
#define NB    8
#define NC    64
#define NPIX  (NB*HW2)         // 524288
#define HW24  16384            // float4-quads per batch image
#define GRID  512              // <= 148*4 so all CTAs are co-resident
#define NTHR  256

// Scratch + sync state (static device globals — allocation-free)
__device__ float g_n1[NPIX];
__device__ float g_n2[NPIX];
__device__ unsigned g_cnt;     // monotonic norm-arrival counter

__global__ void k_reset() { g_cnt = 0; }

// ---------------------------------------------------------------------------
// Split barrier on the NORM chain only.
// arrive: publish this CTA's norm writes (fence) then bump the counter.
// wait(target): spin until all GRID CTAs arrived for that batch.
// Safe: all 512 CTAs co-resident (__launch_bounds__(256,4), 148 SMs).
// ---------------------------------------------------------------------------
__device__ __forceinline__ void norm_arrive() {
    __syncthreads();                       // CTA's norm fully done
    if (threadIdx.x == 0) {
        __threadfence();                   // release g_n writes
        atomicAdd(&g_cnt, 1u);
    }
}

__device__ __forceinline__ void norm_wait(unsigned target) {
    if (threadIdx.x == 0) {
        while (*(volatile unsigned*)&g_cnt < target)
            __nanosleep(64);
        __threadfence();                   // acquire
    }
    __syncthreads();
}

// ---------------------------------------------------------------------------
// Norm phase for batch b: per-pixel channel L1 norms of x1 and x2.
// Block = 32 quads x 8 groups of 8 channels, smem combine.
// Default-cached reads: batch b's x lines stay hot in L2 for blend(b).
// ---------------------------------------------------------------------------
__device__ __forceinline__ void do_norm(const float4* __restrict__ x1,
                                        const float4* __restrict__ x2,
                                        int b,
                                        float4 (*sm1)[32], float4 (*sm2)[32]) {
    int t = threadIdx.x;
    int p = t & 31;                  // quad within block
    int g = t >> 5;                  // channel group 0..7
    int q = blockIdx.x * 32 + p;     // [0, HW24)
    size_t base = ((size_t)b * NC + g * 8) * HW24 + q;

    float4 s1 = make_float4(0.f, 0.f, 0.f, 0.f);
    float4 s2 = make_float4(0.f, 0.f, 0.f, 0.f);
#pragma unroll
    for (int c = 0; c < 8; ++c) {
        float4 a = x1[base + (size_t)c * HW24];
        float4 d = x2[base + (size_t)c * HW24];
        s1.x += fabsf(a.x); s1.y += fabsf(a.y); s1.z += fabsf(a.z); s1.w += fabsf(a.w);
        s2.x += fabsf(d.x); s2.y += fabsf(d.y); s2.z += fabsf(d.z); s2.w += fabsf(d.w);
    }
    sm1[g][p] = s1;
    sm2[g][p] = s2;
    __syncthreads();

    if (t < 32) {
        float4 o = make_float4(0.f, 0.f, 0.f, 0.f);
#pragma unroll
        for (int k = 0; k < 8; ++k) {
            float4 v = sm1[k][t];
            o.x += v.x; o.y += v.y; o.z += v.z; o.w += v.w;
        }
        reinterpret_cast<float4*>(g_n1)[b * HW24 + blockIdx.x * 32 + t] = o;
    } else if (t < 64) {
        int tt = t - 32;
        float4 o = make_float4(0.f, 0.f, 0.f, 0.f);
#pragma unroll
        for (int k = 0; k < 8; ++k) {
            float4 v = sm2[k][tt];
            o.x += v.x; o.y += v.y; o.z += v.z; o.w += v.w;
        }
        reinterpret_cast<float4*>(g_n2)[b * HW24 + blockIdx.x * 32 + tt] = o;
    }
    // smem write/read hazard vs next do_norm is covered by norm_arrive's
    // __syncthreads + next iteration's norm_wait __syncthreads.
}

// ---------------------------------------------------------------------------
// Blend phase for batch b: 3x3 conv + bias on g_n1/g_n2 inline, then
// out = x1*r1 + x2*(1-r1). Thread = one quad x one 8-channel group.
// x re-reads mostly hit L2; __ldcs marks them dead, __stcs streams out.
// ---------------------------------------------------------------------------
__device__ __forceinline__ void do_blend(const float4* __restrict__ x1,
                                         const float4* __restrict__ x2,
                                         float4* __restrict__ out,
                                         const float* __restrict__ w,
                                         const float* __restrict__ bias,
                                         int b) {
    int i = blockIdx.x * NTHR + threadIdx.x;   // [0, 131072)
    int q = i & (HW24 - 1);      // quad within batch image
    int g = i >> 14;             // channel group 0..7
    int y  = q >> 6;             // pixel row
    int x0 = (q & 63) * 4;       // first pixel column of the quad

    float w0 = __ldg(w+0), w1 = __ldg(w+1), w2 = __ldg(w+2);
    float w3 = __ldg(w+3), w4 = __ldg(w+4), w5 = __ldg(w+5);
    float w6 = __ldg(w+6), w7 = __ldg(w+7), w8 = __ldg(w+8);
    float bv = __ldg(bias);

    const float* n1 = g_n1 + b * HW2;
    const float* n2 = g_n2 + b * HW2;

    float c1a0 = 0.f, c1a1 = 0.f, c1a2 = 0.f, c1a3 = 0.f;
    float c2a0 = 0.f, c2a1 = 0.f, c2a2 = 0.f, c2a3 = 0.f;
    bool xm = (x0 > 0), xp = (x0 < HWD - 4);
#pragma unroll
    for (int dy = 0; dy < 3; ++dy) {
        int row = y + dy - 1;
        bool vr = (row >= 0) && (row < HWD);
        int rb = row * HWD + x0;
        float a0 = (vr && xm) ? n1[rb - 1] : 0.f;
        float a1 = vr ? n1[rb + 0] : 0.f;
        float a2 = vr ? n1[rb + 1] : 0.f;
        float a3 = vr ? n1[rb + 2] : 0.f;
        float a4 = vr ? n1[rb + 3] : 0.f;
        float a5 = (vr && xp) ? n1[rb + 4] : 0.f;
        float e0 = (vr && xm) ? n2[rb - 1] : 0.f;
        float e1 = vr ? n2[rb + 0] : 0.f;
        float e2 = vr ? n2[rb + 1] : 0.f;
        float e3 = vr ? n2[rb + 2] : 0.f;
        float e4 = vr ? n2[rb + 3] : 0.f;
        float e5 = (vr && xp) ? n2[rb + 4] : 0.f;
        float wa = (dy == 0) ? w0 : (dy == 1) ? w3 : w6;
        float wb = (dy == 0) ? w1 : (dy == 1) ? w4 : w7;
        float wc = (dy == 0) ? w2 : (dy == 1) ? w5 : w8;
        c1a0 += wa * a0 + wb * a1 + wc * a2;
        c1a1 += wa * a1 + wb * a2 + wc * a3;
        c1a2 += wa * a2 + wb * a3 + wc * a4;
        c1a3 += wa * a3 + wb * a4 + wc * a5;
        c2a0 += wa * e0 + wb * e1 + wc * e2;
        c2a1 += wa * e1 + wb * e2 + wc * e3;
        c2a2 += wa * e2 + wb * e3 + wc * e4;
        c2a3 += wa * e3 + wb * e4 + wc * e5;
    }
    float4 r1, r2;
    {
        float t1, t2;
        t1 = c1a0 + bv; t2 = c2a0 + bv; r1.x = t1 / (t1 + t2); r2.x = 1.f - r1.x;
        t1 = c1a1 + bv; t2 = c2a1 + bv; r1.y = t1 / (t1 + t2); r2.y = 1.f - r1.y;
        t1 = c1a2 + bv; t2 = c2a2 + bv; r1.z = t1 / (t1 + t2); r2.z = 1.f - r1.z;
        t1 = c1a3 + bv; t2 = c2a3 + bv; r1.w = t1 / (t1 + t2); r2.w = 1.f - r1.w;
    }

    size_t base = ((size_t)b * NC + g * 8) * HW24 + q;
#pragma unroll
    for (int c = 0; c < 8; ++c) {
        float4 a = __ldcs(x1 + base + (size_t)c * HW24);
        float4 d = __ldcs(x2 + base + (size_t)c * HW24);
        float4 o;
        o.x = a.x * r1.x + d.x * r2.x;
        o.y = a.y * r1.y + d.y * r2.y;
        o.z = a.z * r1.z + d.z * r2.z;
        o.w = a.w * r1.w + d.w * r2.w;
        __stcs(out + base + (size_t)c * HW24, o);
    }
}

// ---------------------------------------------------------------------------
// Persistent kernel with split-arrive norm chain:
//   norm(0); arrive;
//   for b: wait(all norm(b)); { norm(b+1); arrive; } blend(b);
// blend is OFF the synchronized critical path — its stragglers gate nobody,
// and its traffic fills DRAM gaps around the norm-chain waits.
// ---------------------------------------------------------------------------
__global__ __launch_bounds__(NTHR, 4) void k_fused(const float4* __restrict__ x1,
                                                   const float4* __restrict__ x2,
                                                   float4* __restrict__ out,
                                                   const float* __restrict__ w,
                                                   const float* __restrict__ bias) {
    __shared__ float4 sm1[8][32];
    __shared__ float4 sm2[8][32];

    do_norm(x1, x2, 0, sm1, sm2);
    norm_arrive();
    for (int b = 0; b < NB; ++b) {
        norm_wait((unsigned)(b + 1) * GRID);
        if (b + 1 < NB) {
            do_norm(x1, x2, b + 1, sm1, sm2);
            norm_arrive();
        }
        do_blend(x1, x2, out, w, bias, b);
    }
}

extern "C" void kernel_launch(void* const* d_in, const int* in_sizes, int n_in,
                              void* d_out, int out_size) {
    const float4* x1 = (const float4*)d_in[0];
    const float4* x2 = (const float4*)d_in[1];
    const float*  w  = (const float*)d_in[2];
    const float*  bv = (const float*)d_in[3];
    float4* out = (float4*)d_out;

    k_reset<<<1, 1>>>();
    k_fused<<<GRID, NTHR>>>(x1, x2, out, w, bv);
}

// round 16
// speedup vs baseline: 1.0906x; 1.0037x over previous
#include <cuda_runtime.h>

#define HWD   256
#define HW2   65536            // HWD*HWD
#define NB    8
#define NC    64
#define NPIX  (NB*HW2)         // 524288
#define HW24  16384            // float4-quads per batch image
#define GRID  512              // <= 148*4 so all CTAs are wave-1 co-resident
#define NTHR  256

// Scratch + sync state (static device globals — allocation-free)
__device__ float g_n1[NPIX];
__device__ float g_n2[NPIX];
__device__ unsigned g_nflag[NB * GRID];   // norm-done flag per (batch, CTA)

__global__ void k_reset() {
    int i = blockIdx.x * 256 + threadIdx.x;
    if (i < NB * GRID) g_nflag[i] = 0u;
}

// ---------------------------------------------------------------------------
// Norm phase for batch b: CTA covers quads [32*blk, 32*blk+32) = half a row.
// 32 quads x 8 groups of 8 channels, smem combine. Writers fence their own
// g_n stores; flag is set by t0 after __syncthreads.
// ---------------------------------------------------------------------------
__device__ __forceinline__ void do_norm(const float4* __restrict__ x1,
                                        const float4* __restrict__ x2,
                                        int b,
                                        float4 (*sm1)[32], float4 (*sm2)[32]) {
    int t = threadIdx.x;
    int p = t & 31;                  // quad within block
    int g = t >> 5;                  // channel group 0..7
    int q = blockIdx.x * 32 + p;     // [0, HW24)
    size_t base = ((size_t)b * NC + g * 8) * HW24 + q;

    float4 s1 = make_float4(0.f, 0.f, 0.f, 0.f);
    float4 s2 = make_float4(0.f, 0.f, 0.f, 0.f);
#pragma unroll
    for (int c = 0; c < 8; ++c) {
        float4 a = x1[base + (size_t)c * HW24];
        float4 d = x2[base + (size_t)c * HW24];
        s1.x += fabsf(a.x); s1.y += fabsf(a.y); s1.z += fabsf(a.z); s1.w += fabsf(a.w);
        s2.x += fabsf(d.x); s2.y += fabsf(d.y); s2.z += fabsf(d.z); s2.w += fabsf(d.w);
    }
    sm1[g][p] = s1;
    sm2[g][p] = s2;
    __syncthreads();

    if (t < 32) {
        float4 o = make_float4(0.f, 0.f, 0.f, 0.f);
#pragma unroll
        for (int k = 0; k < 8; ++k) {
            float4 v = sm1[k][t];
            o.x += v.x; o.y += v.y; o.z += v.z; o.w += v.w;
        }
        reinterpret_cast<float4*>(g_n1)[b * HW24 + blockIdx.x * 32 + t] = o;
        __threadfence();   // release this thread's store
    } else if (t < 64) {
        int tt = t - 32;
        float4 o = make_float4(0.f, 0.f, 0.f, 0.f);
#pragma unroll
        for (int k = 0; k < 8; ++k) {
            float4 v = sm2[k][tt];
            o.x += v.x; o.y += v.y; o.z += v.z; o.w += v.w;
        }
        reinterpret_cast<float4*>(g_n2)[b * HW24 + blockIdx.x * 32 + tt] = o;
        __threadfence();   // release this thread's store
    }
    __syncthreads();       // writers done (stores + fences) before flag set
    if (t == 0) atomicExch(&g_nflag[b * GRID + blockIdx.x], 1u);
    // smem reuse hazard vs next do_norm: the flag-wait's __syncthreads (or the
    // next do_norm's first __syncthreads) orders it.
}

// ---------------------------------------------------------------------------
// Wait for the 12 norm CTAs whose rows form the conv halo of this CTA's
// blend region: blend rows [4m, 4m+4) need norm rows [4m-1, 4m+4] ->
// norm CTAs [8m-2, 8m+9] clamped to [0, GRID). Threads 0..11 poll one flag
// each. Deadlock-free: norm never waits, flags are monotonic.
// ---------------------------------------------------------------------------
__device__ __forceinline__ void wait_halo(int b) {
    int m  = blockIdx.x & 63;
    int t  = threadIdx.x;
    if (t < 12) {
        int j = 8 * m - 2 + t;
        if (j < 0) j = 0;
        if (j > GRID - 1) j = GRID - 1;
        volatile unsigned* f = &g_nflag[b * GRID + j];
        while (*f == 0u) __nanosleep(128);
        __threadfence();   // acquire
    }
    __syncthreads();
}

// ---------------------------------------------------------------------------
// Blend phase for batch b: 3x3 conv + bias on g_n inline, then
// out = x1*r1 + x2*(1-r1). Thread = one quad x one 8-channel group;
// CTA covers quads [256m, 256m+256) x group (blk/64).
// x re-reads hit L2 (streamed <=1 batch ago); __ldcs dead-marks, __stcs
// streams out.
// ---------------------------------------------------------------------------
__device__ __forceinline__ void do_blend(const float4* __restrict__ x1,
                                         const float4* __restrict__ x2,
                                         float4* __restrict__ out,
                                         const float* __restrict__ w,
                                         const float* __restrict__ bias,
                                         int b) {
    int i = blockIdx.x * NTHR + threadIdx.x;   // [0, 131072)
    int q = i & (HW24 - 1);      // quad within batch image
    int g = i >> 14;             // channel group 0..7
    int y  = q >> 6;             // pixel row
    int x0 = (q & 63) * 4;       // first pixel column of the quad

    float w0 = __ldg(w+0), w1 = __ldg(w+1), w2 = __ldg(w+2);
    float w3 = __ldg(w+3), w4 = __ldg(w+4), w5 = __ldg(w+5);
    float w6 = __ldg(w+6), w7 = __ldg(w+7), w8 = __ldg(w+8);
    float bv = __ldg(bias);

    const float* n1 = g_n1 + b * HW2;
    const float* n2 = g_n2 + b * HW2;

    float c1a0 = 0.f, c1a1 = 0.f, c1a2 = 0.f, c1a3 = 0.f;
    float c2a0 = 0.f, c2a1 = 0.f, c2a2 = 0.f, c2a3 = 0.f;
    bool xm = (x0 > 0), xp = (x0 < HWD - 4);
#pragma unroll
    for (int dy = 0; dy < 3; ++dy) {
        int row = y + dy - 1;
        bool vr = (row >= 0) && (row < HWD);
        int rb = row * HWD + x0;
        float a0 = (vr && xm) ? n1[rb - 1] : 0.f;
        float a1 = vr ? n1[rb + 0] : 0.f;
        float a2 = vr ? n1[rb + 1] : 0.f;
        float a3 = vr ? n1[rb + 2] : 0.f;
        float a4 = vr ? n1[rb + 3] : 0.f;
        float a5 = (vr && xp) ? n1[rb + 4] : 0.f;
        float e0 = (vr && xm) ? n2[rb - 1] : 0.f;
        float e1 = vr ? n2[rb + 0] : 0.f;
        float e2 = vr ? n2[rb + 1] : 0.f;
        float e3 = vr ? n2[rb + 2] : 0.f;
        float e4 = vr ? n2[rb + 3] : 0.f;
        float e5 = (vr && xp) ? n2[rb + 4] : 0.f;
        float wa = (dy == 0) ? w0 : (dy == 1) ? w3 : w6;
        float wb = (dy == 0) ? w1 : (dy == 1) ? w4 : w7;
        float wc = (dy == 0) ? w2 : (dy == 1) ? w5 : w8;
        c1a0 += wa * a0 + wb * a1 + wc * a2;
        c1a1 += wa * a1 + wb * a2 + wc * a3;
        c1a2 += wa * a2 + wb * a3 + wc * a4;
        c1a3 += wa * a3 + wb * a4 + wc * a5;
        c2a0 += wa * e0 + wb * e1 + wc * e2;
        c2a1 += wa * e1 + wb * e2 + wc * e3;
        c2a2 += wa * e2 + wb * e3 + wc * e4;
        c2a3 += wa * e3 + wb * e4 + wc * e5;
    }
    float4 r1, r2;
    {
        float u, v;
        u = c1a0 + bv; v = c2a0 + bv; r1.x = u / (u + v); r2.x = 1.f - r1.x;
        u = c1a1 + bv; v = c2a1 + bv; r1.y = u / (u + v); r2.y = 1.f - r1.y;
        u = c1a2 + bv; v = c2a2 + bv; r1.z = u / (u + v); r2.z = 1.f - r1.z;
        u = c1a3 + bv; v = c2a3 + bv; r1.w = u / (u + v); r2.w = 1.f - r1.w;
    }

    size_t base = ((size_t)b * NC + g * 8) * HW24 + q;
#pragma unroll
    for (int c = 0; c < 8; ++c) {
        float4 a = __ldcs(x1 + base + (size_t)c * HW24);
        float4 d = __ldcs(x2 + base + (size_t)c * HW24);
        float4 o;
        o.x = a.x * r1.x + d.x * r2.x;
        o.y = a.y * r1.y + d.y * r2.y;
        o.z = a.z * r1.z + d.z * r2.z;
        o.w = a.w * r1.w + d.w * r2.w;
        __stcs(out + base + (size_t)c * HW24, o);
    }
}

// ---------------------------------------------------------------------------
// Persistent kernel with LOCAL halo sync (no global barrier, no convoy):
//   norm(0); flag;
//   for b=1..7:  norm(b); flag;  wait 12 halo flags(b-1);  blend(b-1);
//   wait halo(7); blend(7);
// Norm chain never waits -> DRAM read stream never globally stalls;
// stragglers only delay their 12-CTA neighborhoods.
// ---------------------------------------------------------------------------
__global__ __launch_bounds__(NTHR, 4) void k_ws(const float4* __restrict__ x1,
                                                const float4* __restrict__ x2,
                                                float4* __restrict__ out,
                                                const float* __restrict__ w,
                                                const float* __restrict__ bias) {
    __shared__ float4 sm1[8][32];
    __shared__ float4 sm2[8][32];

    do_norm(x1, x2, 0, sm1, sm2);
    for (int b = 1; b < NB; ++b) {
        do_norm(x1, x2, b, sm1, sm2);
        wait_halo(b - 1);
        do_blend(x1, x2, out, w, bias, b - 1);
    }
    wait_halo(NB - 1);
    do_blend(x1, x2, out, w, bias, NB - 1);
}

extern "C" void kernel_launch(void* const* d_in, const int* in_sizes, int n_in,
                              void* d_out, int out_size) {
    const float4* x1 = (const float4*)d_in[0];
    const float4* x2 = (const float4*)d_in[1];
    const float*  w  = (const float*)d_in[2];
    const float*  bv = (const float*)d_in[3];
    float4* out = (float4*)d_out;

    k_reset<<<(NB * GRID + 255) / 256, 256>>>();
    k_ws<<<GRID, NTHR>>>(x1, x2, out, w, bv);
}